// round 16
// baseline (speedup 1.0000x reference)
#include <cuda_runtime.h>
#include <cuda_fp16.h>
#include <cstdint>

#define VOCAB 100000
#define EMBED 64
#define NPOS  51200          // B*S = 1024*50
#define KIDS  20
#define ROW_BYTES 128        // 64 halves

// W transposed + converted to fp16: [VOCAB, EMBED] = 12.8 MB, L2-resident.
// One row = 128 B = one cache line, 16B-aligned (base is 16B aligned, rows are
// 128B-strided).
__device__ __align__(128) __half g_WTh[(size_t)VOCAB * EMBED];

// ---------------------------------------------------------------------------
// PTX helpers (bulk async copy + mbarrier)
// ---------------------------------------------------------------------------
__device__ __forceinline__ uint32_t smem_u32(const void* p) {
    return (uint32_t)__cvta_generic_to_shared(p);
}

__device__ __forceinline__ void mbar_init(uint32_t mbar, uint32_t count) {
    asm volatile("mbarrier.init.shared.b64 [%0], %1;" :: "r"(mbar), "r"(count) : "memory");
}

__device__ __forceinline__ void mbar_expect_tx(uint32_t mbar, uint32_t bytes) {
    asm volatile("mbarrier.arrive.expect_tx.shared.b64 _, [%0], %1;"
                 :: "r"(mbar), "r"(bytes) : "memory");
}

__device__ __forceinline__ void mbar_wait(uint32_t mbar, uint32_t parity) {
    asm volatile(
        "{\n\t"
        ".reg .pred P;\n\t"
        "WAIT_%=:\n\t"
        "mbarrier.try_wait.parity.acquire.cta.shared::cta.b64 P, [%0], %1, 0x989680;\n\t"
        "@P bra.uni DONE_%=;\n\t"
        "bra.uni WAIT_%=;\n\t"
        "DONE_%=:\n\t"
        "}"
        :: "r"(mbar), "r"(parity) : "memory");
}

// 128B global -> smem bulk copy on the TMA/bulk path (no L1, no registers).
__device__ __forceinline__ void bulk_copy_row(uint32_t dst_smem, const void* src,
                                              uint32_t mbar) {
    asm volatile(
        "cp.async.bulk.shared::cluster.global.mbarrier::complete_tx::bytes "
        "[%0], [%1], %2, [%3];"
        :: "r"(dst_smem), "l"(src), "n"(ROW_BYTES), "r"(mbar) : "memory");
}

// ---------------------------------------------------------------------------
// Kernel 1: transpose + convert  W[64, 100000] f32  ->  g_WTh[100000, 64] f16
// (unchanged from R9; measured at DRAM floor ~5.5us)
// ---------------------------------------------------------------------------
__global__ __launch_bounds__(256) void transpose_W_kernel(const float* __restrict__ W) {
    __shared__ float tile[64][33];
    const int tid = threadIdx.x;
    const int v0  = blockIdx.x * 32;

    #pragma unroll
    for (int i = 0; i < 2; ++i) {
        int j  = tid + i * 256;
        int e  = j >> 3;
        int vq = (j & 7) * 4;
        float4 val = *reinterpret_cast<const float4*>(W + (size_t)e * VOCAB + v0 + vq);
        tile[e][vq + 0] = val.x;
        tile[e][vq + 1] = val.y;
        tile[e][vq + 2] = val.z;
        tile[e][vq + 3] = val.w;
    }
    __syncthreads();

    {
        int v  = tid >> 3;
        int e8 = (tid & 7) * 8;
        __half2 h[4];
        #pragma unroll
        for (int i = 0; i < 4; ++i) {
            h[i] = __floats2half2_rn(tile[e8 + 2 * i][v], tile[e8 + 2 * i + 1][v]);
        }
        *reinterpret_cast<uint4*>(g_WTh + (size_t)(v0 + v) * EMBED + e8) =
            *reinterpret_cast<uint4*>(h);
    }
}

// ---------------------------------------------------------------------------
// Kernel 2: embedding-bag gather via cp.async.bulk (TMA path).
// 8 warps/block, each warp owns 4 positions, double-buffered:
//   issue(i): lane 0 expect_tx(2560); lanes 0..19 each bulk-copy one 128B row
//             into buf[i&1].
//   reduce(i): wait mbar parity, 20x LDS.32 per lane (bank-conflict-free),
//              fp32 accumulate, +bias, float2 store.
// Pipeline: issue0, issue1, {wait0,red0,issue2}, {wait1,red1,issue3}, wait2.. 
// ---------------------------------------------------------------------------
#define WARPS_PB   8
#define POS_PW     4          // positions per warp
#define POS_PB     (WARPS_PB * POS_PW)   // 32
#define STAGE_B    (KIDS * ROW_BYTES)    // 2560 bytes per position

__global__ __launch_bounds__(256) void gather_sum_kernel(
    const int*   __restrict__ ids,    // [NPOS, KIDS]
    const float* __restrict__ bias,   // [EMBED]
    float*       __restrict__ out)    // [NPOS, EMBED]
{
    __shared__ __align__(128) char buf[WARPS_PB][2][STAGE_B];  // 40 KB
    __shared__ __align__(8) unsigned long long mbar_store[WARPS_PB][2];

    const int tid  = threadIdx.x;
    const int warp = tid >> 5;
    const int lane = tid & 31;
    const int pos0 = blockIdx.x * POS_PB + warp * POS_PW;

    // Init this block's 16 mbarriers (count=1: only the expect_tx arrives).
    if (tid < WARPS_PB * 2)
        mbar_init(smem_u32(&mbar_store[tid >> 1][tid & 1]), 1);
    __syncthreads();

    const uint32_t mbar[2] = { smem_u32(&mbar_store[warp][0]),
                               smem_u32(&mbar_store[warp][1]) };
    const uint32_t bufa[2] = { smem_u32(&buf[warp][0][0]),
                               smem_u32(&buf[warp][1][0]) };

    // Per-lane bias (fp32, exact).
    const float2 bb = __ldg(reinterpret_cast<const float2*>(bias + lane * 2));

    // issue(i): load my id (lane<20), expect_tx, bulk-copy my row.
    auto issue = [&](int i) {
        const int b = i & 1;
        if (lane == 0) mbar_expect_tx(mbar[b], STAGE_B);
        __syncwarp();
        if (lane < KIDS) {
            int id = __ldg(ids + (size_t)(pos0 + i) * KIDS + lane);
            bulk_copy_row(bufa[b] + lane * ROW_BYTES,
                          g_WTh + (size_t)id * EMBED, mbar[b]);
        }
    };

    issue(0);
    issue(1);

    #pragma unroll
    for (int i = 0; i < POS_PW; ++i) {
        const int b = i & 1;
        mbar_wait(mbar[b], (i >> 1) & 1);

        // Reduce 20 rows: lane reads half2 at row k, elem offset lane*4.
        const char* base = &buf[warp][b][0];
        float2 accA = make_float2(0.f, 0.f);
        float2 accB = make_float2(0.f, 0.f);
        #pragma unroll
        for (int k = 0; k < KIDS; k += 2) {
            __half2 h0 = *reinterpret_cast<const __half2*>(base + k * ROW_BYTES + lane * 4);
            __half2 h1 = *reinterpret_cast<const __half2*>(base + (k + 1) * ROW_BYTES + lane * 4);
            float2 f0 = __half22float2(h0);
            float2 f1 = __half22float2(h1);
            accA.x += f0.x; accA.y += f0.y;
            accB.x += f1.x; accB.y += f1.y;
        }
        accA.x += accB.x + bb.x;
        accA.y += accB.y + bb.y;

        // Buffer b is now free; issue the next position into it.
        __syncwarp();
        if (i + 2 < POS_PW) issue(i + 2);

        *reinterpret_cast<float2*>(out + (size_t)(pos0 + i) * EMBED + lane * 2) = accA;
    }
}

// ---------------------------------------------------------------------------
// inputs: 0 = content_input int32 [B,S,K], 1 = W f32 [E,V], 2 = b f32 [E]
// output: f32 [B,S,E]
// ---------------------------------------------------------------------------
extern "C" void kernel_launch(void* const* d_in, const int* in_sizes, int n_in,
                              void* d_out, int out_size) {
    const int*   ids  = (const int*)d_in[0];
    const float* W    = (const float*)d_in[1];
    const float* bias = (const float*)d_in[2];
    float*       out  = (float*)d_out;

    transpose_W_kernel<<<VOCAB / 32, 256>>>(W);                // 3125 blocks
    gather_sum_kernel<<<NPOS / POS_PB, 256>>>(ids, bias, out); // 1600 blocks
}

// round 17
// speedup vs baseline: 1.5567x; 1.5567x over previous
#include <cuda_runtime.h>
#include <cuda_fp16.h>
#include <cstdint>

#define VOCAB 100000
#define EMBED 64
#define NPOS  51200          // B*S = 1024*50
#define KIDS  20

// W transposed + converted to fp16: [VOCAB, EMBED] = 12.8 MB, L2-resident.
// One row = 64 halves = 128 B = one cache line.
__device__ __align__(128) __half g_WTh[(size_t)VOCAB * EMBED];

// ---------------------------------------------------------------------------
// Kernel 1: transpose + convert  W[64, 100000] f32  ->  g_WTh[100000, 64] f16
// (byte-identical to R9; measured 4.8-6.1us, near DRAM floor)
// ---------------------------------------------------------------------------
__global__ __launch_bounds__(256) void transpose_W_kernel(const float* __restrict__ W) {
    __shared__ float tile[64][33];
    const int tid = threadIdx.x;
    const int v0  = blockIdx.x * 32;

    #pragma unroll
    for (int i = 0; i < 2; ++i) {
        int j  = tid + i * 256;
        int e  = j >> 3;
        int vq = (j & 7) * 4;
        float4 val = *reinterpret_cast<const float4*>(W + (size_t)e * VOCAB + v0 + vq);
        tile[e][vq + 0] = val.x;
        tile[e][vq + 1] = val.y;
        tile[e][vq + 2] = val.z;
        tile[e][vq + 3] = val.w;
    }
    __syncthreads();

    {
        int v  = tid >> 3;
        int e8 = (tid & 7) * 8;
        __half2 h[4];
        #pragma unroll
        for (int i = 0; i < 4; ++i) {
            h[i] = __floats2half2_rn(tile[e8 + 2 * i][v], tile[e8 + 2 * i + 1][v]);
        }
        *reinterpret_cast<uint4*>(g_WTh + (size_t)(v0 + v) * EMBED + e8) =
            *reinterpret_cast<uint4*>(h);
    }
}

// ---------------------------------------------------------------------------
// Kernel 2: embedding-bag gather — fp16 clone of the R7 shape.
// 16 lanes per position (2 positions/warp). Lane owns 8 bytes (4 halves) of
// the 128B row -> each half-warp LDG.64 covers exactly one row with a
// uniform base (warp op = 2 contiguous-line requests, like R7's winner).
// All 20 loads pre-batched (independent), fp32 accumulation.
// 16 positions per 256-thread block.
// ---------------------------------------------------------------------------
__global__ __launch_bounds__(256) void gather_sum_kernel(
    const int*   __restrict__ ids,    // [NPOS, KIDS]
    const float* __restrict__ bias,   // [EMBED]
    float*       __restrict__ out)    // [NPOS, EMBED]
{
    __shared__ int sids[16 * KIDS];   // 320 ids for this block's 16 positions

    const int tid  = threadIdx.x;
    const int pos0 = blockIdx.x * 16;

    // Coalesced cooperative id load (320 ints = 1280B).
    for (int i = tid; i < 16 * KIDS; i += 256)
        sids[i] = ids[(size_t)pos0 * KIDS + i];
    __syncthreads();

    const int p   = tid >> 4;         // local position 0..15
    const int sub = tid & 15;         // owns halves [4*sub, 4*sub+4)
    const int* myids = sids + p * KIDS;
    const __half* wt = g_WTh + (size_t)sub * 4;

    // Pre-read ids (broadcast LDS, uniform per half-warp).
    int kid[KIDS];
    #pragma unroll
    for (int k = 0; k < KIDS; ++k) kid[k] = myids[k];

    // 20 independent LDG.64 loads — full batch in flight.
    uint2 w[KIDS];
    #pragma unroll
    for (int k = 0; k < KIDS; ++k)
        w[k] = *reinterpret_cast<const uint2*>(wt + (size_t)kid[k] * EMBED);

    // fp32 accumulation, two independent chains.
    float2 aA = make_float2(0.f, 0.f), aB = make_float2(0.f, 0.f);
    float2 bA = make_float2(0.f, 0.f), bB = make_float2(0.f, 0.f);
    #pragma unroll
    for (int k = 0; k < KIDS; k += 2) {
        float2 f0 = __half22float2(*reinterpret_cast<const __half2*>(&w[k].x));
        float2 f1 = __half22float2(*reinterpret_cast<const __half2*>(&w[k].y));
        float2 g0 = __half22float2(*reinterpret_cast<const __half2*>(&w[k + 1].x));
        float2 g1 = __half22float2(*reinterpret_cast<const __half2*>(&w[k + 1].y));
        aA.x += f0.x; aA.y += f0.y;
        aB.x += f1.x; aB.y += f1.y;
        bA.x += g0.x; bA.y += g0.y;
        bB.x += g1.x; bB.y += g1.y;
    }
    aA.x += bA.x; aA.y += bA.y;
    aB.x += bB.x; aB.y += bB.y;

    // Bias (fp32, exact) + output: float4 per lane, 256B contiguous/half-warp.
    const float4 bb = __ldg(reinterpret_cast<const float4*>(bias + sub * 4));
    float4 r = make_float4(aA.x + bb.x, aA.y + bb.y, aB.x + bb.z, aB.y + bb.w);

    *reinterpret_cast<float4*>(out + (size_t)(pos0 + p) * EMBED + sub * 4) = r;
}

// ---------------------------------------------------------------------------
// inputs: 0 = content_input int32 [B,S,K], 1 = W f32 [E,V], 2 = b f32 [E]
// output: f32 [B,S,E]
// ---------------------------------------------------------------------------
extern "C" void kernel_launch(void* const* d_in, const int* in_sizes, int n_in,
                              void* d_out, int out_size) {
    const int*   ids  = (const int*)d_in[0];
    const float* W    = (const float*)d_in[1];
    const float* bias = (const float*)d_in[2];
    float*       out  = (float*)d_out;

    transpose_W_kernel<<<VOCAB / 32, 256>>>(W);            // 3125 blocks
    gather_sum_kernel<<<NPOS / 16, 256>>>(ids, bias, out); // 3200 blocks
}